// round 17
// baseline (speedup 1.0000x reference)
#include <cuda_runtime.h>
#include <cuda_device_runtime_api.h>

// Fused confusion-matrix reduction.
//   y_pred, y_true: [16, 3, 512, 512] f32 -> out [B*C, 4] = [tp, tn, fp, fn]
// tp = sum(p*t); fp = sum(p) - tp; fn = sum(t) - tp; tn = N - sum(p) - sum(t) + tp.
//
// R15 insight: inputs (100.66 MB) fit in the ~126 MB L2; under graph-replay
// timing the stream is L2-resident and LTS-path-limited, not HBM-limited.
// sm_103a ptxas only allows .L2::evict_last on 256-bit loads -> use
// ld.global.nc.L2::evict_last.v8.b32 (LDG.E.256): keeps the working set
// pinned in L2 AND halves LSU/L1tex issue count vs 128-bit loads.
//
// Structure (measured fastest, 12.8us): zero kernel first; streaming reduce
// PDL-launched (overlaps the zero kernel); each block atomicAdds its 4
// transformed partials directly into d_out. 768 CTAs = 16/slice, one wave.

#define SLICES 48                       // B*C
#define N_PER_SLICE (512 * 512)         // 262144 elements per slice
#define BLOCKS_PER_SLICE 16
#define THREADS 256
#define NBLOCKS (SLICES * BLOCKS_PER_SLICE)                       // 768
#define N_PER_BLOCK (N_PER_SLICE / BLOCKS_PER_SLICE)              // 16384
#define V8_PER_BLOCK (N_PER_BLOCK / 8)                            // 2048 vec8
#define V8_PER_THREAD (V8_PER_BLOCK / THREADS)                    // 8
#define OUTER 2
#define INNER 4                          // 4 p-vec8 + 4 t-vec8 per burst

struct f8 { float a0, a1, a2, a3, a4, a5, a6, a7; };

// 256-bit non-coherent load with L2 evict_last (keep resident across replays).
__device__ __forceinline__ f8 ldg256_el(const float* p) {
    f8 v;
    asm("ld.global.nc.L2::evict_last.v8.b32 {%0,%1,%2,%3,%4,%5,%6,%7}, [%8];"
        : "=f"(v.a0), "=f"(v.a1), "=f"(v.a2), "=f"(v.a3),
          "=f"(v.a4), "=f"(v.a5), "=f"(v.a6), "=f"(v.a7)
        : "l"(p));
    return v;
}

__global__ void cm_zero_kernel(float* __restrict__ out, int n) {
    const int i = threadIdx.x;
    if (i < n) out[i] = 0.0f;
}

__global__ __launch_bounds__(THREADS)
void cm_reduce_kernel(const float* __restrict__ p, const float* __restrict__ t,
                      float* __restrict__ out) {
    const int blk = blockIdx.x;                         // 0 .. 767
    // Element offset of this thread's first vec8.
    const long base = (long)blk * N_PER_BLOCK + (long)threadIdx.x * 8;

    float sp = 0.0f, st = 0.0f, spt = 0.0f;

#pragma unroll 1
    for (int i = 0; i < OUTER; i++) {
        f8 pv[INNER], tv[INNER];
#pragma unroll
        for (int j = 0; j < INNER; j++) {
            const long off = base + (long)(i * INNER + j) * (THREADS * 8);
            pv[j] = ldg256_el(p + off);
            tv[j] = ldg256_el(t + off);
        }
#pragma unroll
        for (int j = 0; j < INNER; j++) {
            sp  += ((pv[j].a0 + pv[j].a1) + (pv[j].a2 + pv[j].a3))
                 + ((pv[j].a4 + pv[j].a5) + (pv[j].a6 + pv[j].a7));
            st  += ((tv[j].a0 + tv[j].a1) + (tv[j].a2 + tv[j].a3))
                 + ((tv[j].a4 + tv[j].a5) + (tv[j].a6 + tv[j].a7));
            spt += ((pv[j].a0 * tv[j].a0 + pv[j].a1 * tv[j].a1)
                 +  (pv[j].a2 * tv[j].a2 + pv[j].a3 * tv[j].a3))
                 + ((pv[j].a4 * tv[j].a4 + pv[j].a5 * tv[j].a5)
                 +  (pv[j].a6 * tv[j].a6 + pv[j].a7 * tv[j].a7));
        }
    }

    // Intra-block tree reduction (warp shuffles + smem).
#pragma unroll
    for (int off = 16; off > 0; off >>= 1) {
        sp  += __shfl_down_sync(0xFFFFFFFFu, sp,  off);
        st  += __shfl_down_sync(0xFFFFFFFFu, st,  off);
        spt += __shfl_down_sync(0xFFFFFFFFu, spt, off);
    }

    __shared__ float sm[3][THREADS / 32];
    const int wid = threadIdx.x >> 5;
    const int lid = threadIdx.x & 31;
    if (lid == 0) {
        sm[0][wid] = sp;
        sm[1][wid] = st;
        sm[2][wid] = spt;
    }
    __syncthreads();

    if (threadIdx.x == 0) {
        float a = 0.0f, b = 0.0f, c = 0.0f;
#pragma unroll
        for (int w = 0; w < THREADS / 32; w++) {
            a += sm[0][w];
            b += sm[1][w];
            c += sm[2][w];
        }
        // Ensure the zero kernel's writes are visible (satisfied long ago —
        // the zero kernel completed while we streamed).
        cudaGridDependencySynchronize();

        const int s = blk >> 4;                         // slice index
        const float nchunk = (float)N_PER_BLOCK;
        atomicAdd(&out[s * 4 + 0], c);                  // tp
        atomicAdd(&out[s * 4 + 1], nchunk - a - b + c); // tn
        atomicAdd(&out[s * 4 + 2], a - c);              // fp
        atomicAdd(&out[s * 4 + 3], b - c);              // fn
    }
}

extern "C" void kernel_launch(void* const* d_in, const int* in_sizes, int n_in,
                              void* d_out, int out_size) {
    const float* p = (const float*)d_in[0];   // y_pred
    const float* t = (const float*)d_in[1];   // y_true
    float* out = (float*)d_out;

    // Tiny zeroing kernel first.
    cm_zero_kernel<<<1, 256>>>(out, out_size);

    // PDL launch of the streaming reduce: starts immediately, overlapping the
    // zero kernel; blocks only at the grid-dependency sync before its atomics.
    cudaLaunchConfig_t cfg = {};
    cfg.gridDim = dim3(NBLOCKS, 1, 1);
    cfg.blockDim = dim3(THREADS, 1, 1);
    cfg.dynamicSmemBytes = 0;
    cfg.stream = 0;  // same (captured) default stream
    cudaLaunchAttribute attrs[1];
    attrs[0].id = cudaLaunchAttributeProgrammaticStreamSerialization;
    attrs[0].val.programmaticStreamSerializationAllowed = 1;
    cfg.attrs = attrs;
    cfg.numAttrs = 1;
    cudaLaunchKernelEx(&cfg, cm_reduce_kernel, p, t, out);
}